// round 1
// baseline (speedup 1.0000x reference)
#include <cuda_runtime.h>
#include <math.h>

#define LOD   64
#define LSD   128
#define ORG   128
#define KC    16
#define BAND  6
#define BMAX  8192
#define BAS_ELEMS (4*KC*BAND*LOD)   /* 24576 */
#define MAXPART 1024

// Scratch (static device arrays; no allocation in kernel_launch)
__device__ float g_c[BMAX*LOD];        // c = x@W_covar.T + b_covar
__device__ float g_obs[BMAX*LOD];      // obs_mean
__device__ float g_bas[BAS_ELEMS];     // banded basis, layout [blk][k][d][i]
__device__ float g_partial[MAXPART];   // per-block |c| partial sums

// ---------------------------------------------------------------------------
// Kernel 1: per-row matvecs (h, obs_mean, c), |c| partial sums, and a one-shot
// coalescing pass that extracts the banded basis into g_bas.
// Block: 256 threads = 8 warps, each warp handles 4 rows. Grid = B/32.
// ---------------------------------------------------------------------------
__global__ __launch_bounds__(256) void rkn_k1(
    const float* __restrict__ input,
    const float* __restrict__ W_mean,  const float* __restrict__ b_mean,
    const float* __restrict__ W_covar, const float* __restrict__ b_covar,
    const float* __restrict__ W_norm,  const float* __restrict__ b_norm,
    const float* __restrict__ tm11, const float* __restrict__ tm12,
    const float* __restrict__ tm21, const float* __restrict__ tm22,
    int B)
{
    extern __shared__ float smem[];
    float* sWT  = smem;                  // [128][130]: cols 0..63 Wmean^T, 64..127 Wcovar^T
    float* sWnT = sWT  + 128*130;        // [64][65]:  Wnorm^T
    float* sx   = sWnT + 64*65;          // 8 warps * 4 rows * 128
    float* sh   = sx   + 8*4*128;        // 8 warps * 4 rows * 64
    float* sred = sh   + 8*4*64;         // 8

    const int tid  = threadIdx.x;
    const int lane = tid & 31;
    const int warp = tid >> 5;

    // --- one-shot banded basis extraction (grid covers 24576 elems) ---
    {
        int gidx = blockIdx.x * blockDim.x + tid;
        if (gidx < BAS_ELEMS) {
            int i   = gidx & 63;
            int d   = (gidx >> 6) % BAND;
            int k   = (gidx / (64*BAND)) & 15;
            int blk = gidx / (64*BAND*KC);
            const float* tm = (blk==0)?tm11 : (blk==1)?tm12 : (blk==2)?tm21 : tm22;
            int j = i + d - 3;  // band offsets -3..+2
            float v = (j >= 0 && j < LOD) ? tm[k*LOD*LOD + i*LOD + j] : 0.f;
            g_bas[gidx] = v;
        }
    }

    // --- stage transposed weights into padded shared (conflict-free reads) ---
    for (int idx = tid; idx < LOD*ORG; idx += blockDim.x) {
        int i = idx >> 7;       // 0..63
        int j = idx & 127;      // 0..127
        sWT[j*130 + i]      = W_mean[idx];
        sWT[j*130 + 64 + i] = W_covar[idx];
    }
    for (int idx = tid; idx < LOD*LOD; idx += blockDim.x) {
        int i = idx >> 6;
        int j = idx & 63;
        sWnT[j*65 + i] = W_norm[idx];
    }
    __syncthreads();

    const int row0 = (blockIdx.x * 8 + warp) * 4;
    float acc = 0.f;
    float* mysx = sx + warp*4*128;
    float* mysh = sh + warp*4*64;

    if (row0 + 3 < B) {
        // load 4 rows of x
        #pragma unroll
        for (int r = 0; r < 4; r++) {
            const float* xin = input + (size_t)(row0 + r) * ORG;
            mysx[r*128 + lane]      = xin[lane];
            mysx[r*128 + lane + 32] = xin[lane + 32];
            mysx[r*128 + lane + 64] = xin[lane + 64];
            mysx[r*128 + lane + 96] = xin[lane + 96];
        }
        __syncwarp();

        float h0[4] = {0,0,0,0}, h1[4] = {0,0,0,0};
        float c0[4] = {0,0,0,0}, c1[4] = {0,0,0,0};
        #pragma unroll 4
        for (int j = 0; j < 128; j++) {
            float wh0 = sWT[j*130 + lane];
            float wh1 = sWT[j*130 + 32 + lane];
            float wc0 = sWT[j*130 + 64 + lane];
            float wc1 = sWT[j*130 + 96 + lane];
            #pragma unroll
            for (int r = 0; r < 4; r++) {
                float xv = mysx[r*128 + j];
                h0[r] += wh0*xv; h1[r] += wh1*xv;
                c0[r] += wc0*xv; c1[r] += wc1*xv;
            }
        }
        float bm0 = b_mean[lane],  bm1 = b_mean[lane+32];
        float bc0 = b_covar[lane], bc1 = b_covar[lane+32];
        #pragma unroll
        for (int r = 0; r < 4; r++) {
            h0[r] += bm0; h1[r] += bm1;
            float cc0 = c0[r] + bc0;
            float cc1 = c1[r] + bc1;
            size_t rb = (size_t)(row0 + r) * 64;
            g_c[rb + lane]      = cc0;
            g_c[rb + lane + 32] = cc1;
            acc += fabsf(cc0) + fabsf(cc1);
            mysh[r*64 + lane]      = h0[r];
            mysh[r*64 + lane + 32] = h1[r];
        }
        __syncwarp();

        float n0[4] = {0,0,0,0}, n1[4] = {0,0,0,0};
        #pragma unroll 4
        for (int j = 0; j < 64; j++) {
            float w0 = sWnT[j*65 + lane];
            float w1 = sWnT[j*65 + lane + 32];
            #pragma unroll
            for (int r = 0; r < 4; r++) {
                float hv = mysh[r*64 + j];
                n0[r] += w0*hv; n1[r] += w1*hv;
            }
        }
        float bn0 = b_norm[lane], bn1 = b_norm[lane+32];
        #pragma unroll
        for (int r = 0; r < 4; r++) {
            float v0 = n0[r] + bn0;
            float v1 = n1[r] + bn1;
            v0 = (v0 > 0.f) ? (v0 + 1.f) : expf(v0);  // elu(x)+1
            v1 = (v1 > 0.f) ? (v1 + 1.f) : expf(v1);
            size_t rb = (size_t)(row0 + r) * 64;
            g_obs[rb + lane]      = v0;
            g_obs[rb + lane + 32] = v1;
        }
    }

    // deterministic block reduction of |c| partial
    #pragma unroll
    for (int o = 16; o; o >>= 1) acc += __shfl_xor_sync(0xffffffffu, acc, o);
    if (lane == 0) sred[warp] = acc;
    __syncthreads();
    if (tid == 0) {
        float s = 0.f;
        #pragma unroll
        for (int w = 0; w < 8; w++) s += sred[w];
        g_partial[blockIdx.x] = s;
    }
}

// ---------------------------------------------------------------------------
// Kernel 2: coeff softmax + banded transition contraction + Kalman update.
// Block: 512 threads = 16 warps, each warp processes 4 rows jointly so the
// shared basis reads are amortized 4x. Grid = B/64.
// ---------------------------------------------------------------------------
__global__ __launch_bounds__(512, 1) void rkn_k2(
    const float* __restrict__ state,
    const float* __restrict__ W_coef, const float* __restrict__ b_coef,
    const float* __restrict__ log_tc,
    float* __restrict__ out, int B, int nblk1)
{
    extern __shared__ float smem[];
    float* sbas = smem;                   // 24576: [blk][k][d][i]
    float* sWcT = sbas + BAS_ELEMS;       // [128][16] W_coef^T
    float* sS   = sWcT + 2048;            // [32]
    float* sred = sS + 32;                // [1024]
    float* swb  = sred + MAXPART;         // 16 warps * 1344

    const int tid  = threadIdx.x;
    const int lane = tid & 31;
    const int warp = tid >> 5;

    for (int idx = tid; idx < BAS_ELEMS; idx += 512) sbas[idx] = g_bas[idx];
    for (int idx = tid; idx < KC*LSD; idx += 512) {
        int k = idx >> 7;
        int j = idx & 127;
        sWcT[j*16 + k] = W_coef[idx];
    }
    for (int idx = tid; idx < nblk1; idx += 512) sred[idx] = g_partial[idx];
    __syncthreads();
    if (tid == 0) {
        float s = 0.f;
        for (int b = 0; b < nblk1; b++) s += sred[b];
        sS[0] = s;
    }
    __syncthreads();
    const float invS = 1.f / sS[0];

    float* wb  = swb + warp*1344;
    float* pmb = wb;            // [4][128]
    float* cub = wb + 512;      // [4][64]
    float* clb = wb + 768;      // [4][64]
    float* csb = wb + 1024;     // [4][64]
    float* lgb = wb + 1280;     // [4][16]

    const int row0 = (blockIdx.x * 16 + warp) * 4;
    if (row0 + 3 >= B + 3) return;   // warp-uniform
    if (row0 >= B) return;

    #pragma unroll
    for (int r = 0; r < 4; r++) {
        const float* st = state + (size_t)(row0 + r) * 320;
        pmb[r*128 + lane]      = st[lane];
        pmb[r*128 + lane + 32] = st[lane + 32];
        pmb[r*128 + lane + 64] = st[lane + 64];
        pmb[r*128 + lane + 96] = st[lane + 96];
        cub[r*64 + lane]       = st[128 + lane];
        cub[r*64 + lane + 32]  = st[160 + lane];
        clb[r*64 + lane]       = st[192 + lane];
        clb[r*64 + lane + 32]  = st[224 + lane];
        csb[r*64 + lane]       = st[256 + lane];
        csb[r*64 + lane + 32]  = st[288 + lane];
    }
    __syncwarp();

    // logits: 2 threads per logit, 64-elem halves each
    {
        const int k    = lane & 15;
        const int part = lane >> 4;
        float a0 = 0.f, a1 = 0.f, a2 = 0.f, a3 = 0.f;
        const float* wp  = sWcT + part*64*16 + k;
        const float* pmp = pmb + part*64;
        #pragma unroll 8
        for (int j = 0; j < 64; j++) {
            float w = wp[j*16];
            a0 += w * pmp[j];
            a1 += w * pmp[128 + j];
            a2 += w * pmp[256 + j];
            a3 += w * pmp[384 + j];
        }
        a0 += __shfl_xor_sync(0xffffffffu, a0, 16);
        a1 += __shfl_xor_sync(0xffffffffu, a1, 16);
        a2 += __shfl_xor_sync(0xffffffffu, a2, 16);
        a3 += __shfl_xor_sync(0xffffffffu, a3, 16);
        if (lane < 16) {
            float bk = b_coef[k];
            lgb[k]      = a0 + bk;
            lgb[16 + k] = a1 + bk;
            lgb[32 + k] = a2 + bk;
            lgb[48 + k] = a3 + bk;
        }
    }
    __syncwarp();

    // softmax per row (redundant per lane, registers)
    float coef[4][16];
    #pragma unroll
    for (int r = 0; r < 4; r++) {
        float m = -1e30f;
        #pragma unroll
        for (int k = 0; k < 16; k++) { float v = lgb[r*16 + k]; coef[r][k] = v; m = fmaxf(m, v); }
        float s = 0.f;
        #pragma unroll
        for (int k = 0; k < 16; k++) { float e = expf(coef[r][k] - m); coef[r][k] = e; s += e; }
        float inv = 1.f / s;
        #pragma unroll
        for (int k = 0; k < 16; k++) coef[r][k] *= inv;
    }

    #pragma unroll
    for (int half = 0; half < 2; half++) {
        const int i = lane + half*32;
        float pu[4]  = {0,0,0,0}, pl[4]  = {0,0,0,0};
        float qcu[4] = {0,0,0,0}, qcl[4] = {0,0,0,0}, qcs[4] = {0,0,0,0};

        #pragma unroll
        for (int d = 0; d < BAND; d++) {
            float B11[4] = {0,0,0,0}, B12[4] = {0,0,0,0};
            float B21[4] = {0,0,0,0}, B22[4] = {0,0,0,0};
            const float* base = sbas + d*64 + i;
            #pragma unroll
            for (int k = 0; k < KC; k++) {
                float t11 = base[(0*KC + k)*BAND*64];
                float t12 = base[(1*KC + k)*BAND*64];
                float t21 = base[(2*KC + k)*BAND*64];
                float t22 = base[(3*KC + k)*BAND*64];
                #pragma unroll
                for (int r = 0; r < 4; r++) {
                    float ck = coef[r][k];
                    B11[r] += ck*t11; B12[r] += ck*t12;
                    B21[r] += ck*t21; B22[r] += ck*t22;
                }
            }
            int j = i + d - 3;
            if (j >= 0 && j < 64) {
                #pragma unroll
                for (int r = 0; r < 4; r++) {
                    float pmu = pmb[r*128 + j], pml = pmb[r*128 + 64 + j];
                    float CU = cub[r*64 + j], CL = clb[r*64 + j], CS = csb[r*64 + j];
                    float b11 = B11[r], b12 = B12[r], b21 = B21[r], b22 = B22[r];
                    pu[r]  += b11*pmu + b12*pml;
                    pl[r]  += b21*pmu + b22*pml;
                    qcu[r] += b11*b11*CU + 2.f*b11*b12*CS + b12*b12*CL;
                    qcl[r] += b21*b21*CU + 2.f*b21*b22*CS + b22*b22*CL;
                    qcs[r] += b21*b11*CU + (b22*b11 + b21*b12)*CS + b22*b12*CL;
                }
            }
        }

        float lu = log_tc[i];
        float ll = log_tc[64 + i];
        float tcu = (lu > 0.f) ? (lu + 1.f) : expf(lu);
        float tcl = (ll > 0.f) ? (ll + 1.f) : expf(ll);

        #pragma unroll
        for (int r = 0; r < 4; r++) {
            size_t rb = (size_t)(row0 + r);
            float PCU = qcu[r] + tcu;
            float PCL = qcl[r] + tcl;
            float PCS = qcs[r];
            float oc  = g_c[rb*64 + i] * invS;
            float rden = 1.f / (PCU + oc);
            float qu = PCU * rden;
            float ql = PCS * rden;
            float res = g_obs[rb*64 + i] - pu[r];
            float cf = 1.f - qu;
            float* o = out + rb*320;
            o[i]        = pu[r] + qu*res;
            o[64 + i]   = pl[r] + ql*res;
            o[128 + i]  = cf * PCU;
            o[192 + i]  = PCL - ql*PCS;
            o[256 + i]  = cf * PCS;
        }
    }
}

extern "C" void kernel_launch(void* const* d_in, const int* in_sizes, int n_in,
                              void* d_out, int out_size) {
    const float* input   = (const float*)d_in[0];
    const float* state   = (const float*)d_in[1];
    const float* W_mean  = (const float*)d_in[2];
    const float* b_mean  = (const float*)d_in[3];
    const float* W_covar = (const float*)d_in[4];
    const float* b_covar = (const float*)d_in[5];
    const float* W_norm  = (const float*)d_in[6];
    const float* b_norm  = (const float*)d_in[7];
    const float* W_coef  = (const float*)d_in[8];
    const float* b_coef  = (const float*)d_in[9];
    const float* tm11    = (const float*)d_in[10];
    const float* tm12    = (const float*)d_in[11];
    const float* tm21    = (const float*)d_in[12];
    const float* tm22    = (const float*)d_in[13];
    const float* log_tc  = (const float*)d_in[14];
    float* out = (float*)d_out;

    int B = in_sizes[0] / ORG;            // 8192
    int g1 = (B + 31) / 32;               // 256
    int g2 = (B + 63) / 64;               // 128

    size_t sh1 = (size_t)(128*130 + 64*65 + 8*4*128 + 8*4*64 + 8) * sizeof(float);
    size_t sh2 = (size_t)(BAS_ELEMS + 2048 + 32 + MAXPART + 16*1344) * sizeof(float);

    cudaFuncSetAttribute(rkn_k1, cudaFuncAttributeMaxDynamicSharedMemorySize, (int)sh1);
    cudaFuncSetAttribute(rkn_k2, cudaFuncAttributeMaxDynamicSharedMemorySize, (int)sh2);

    rkn_k1<<<g1, 256, sh1>>>(input, W_mean, b_mean, W_covar, b_covar,
                             W_norm, b_norm, tm11, tm12, tm21, tm22, B);
    rkn_k2<<<g2, 512, sh2>>>(state, W_coef, b_coef, log_tc, out, B, g1);
}